// round 10
// baseline (speedup 1.0000x reference)
#include <cuda_runtime.h>

#define NB 8
#define NS 2048
#define ND 768
#define NH 64
#define NQT 32            // q-tiles of 64
#define SKA 68            // attn smem stride (floats), 68 % 32 == 4 -> conflict-free LDSM
#define PXS 36            // proj X smem stride   (36 % 32 == 4)
#define PWS 36            // proj W smem stride   (36 % 32 == 4)

__device__ float g_Q[NB * NS * NH];
__device__ float g_K[NB * NS * NH];
__device__ float g_V[NB * NS * NH];
__device__ float g_Wt[3 * NH * ND];     // [n=z*64+h][k], tf32-rounded bits

// split-K partials: [half][b][qt] -> 64x64 unnormalized O, plus per-row m,l
__device__ float g_Op[2 * NB * NQT * 64 * 64];
__device__ float g_M[2 * NB * NQT * 64];
__device__ float g_L[2 * NB * NQT * 64];

// ---------------------------------------------------------------------------
// helpers
// ---------------------------------------------------------------------------
__device__ __forceinline__ unsigned f2tf(float f) {
    unsigned u;
    asm("cvt.rna.tf32.f32 %0, %1;" : "=r"(u) : "f"(f));
    return u;
}
__device__ __forceinline__ uint4 f4tf(float4 v) {
    uint4 r;
    r.x = f2tf(v.x); r.y = f2tf(v.y); r.z = f2tf(v.z); r.w = f2tf(v.w);
    return r;
}
__device__ __forceinline__ void mma8(float c[4],
                                     unsigned a0, unsigned a1, unsigned a2, unsigned a3,
                                     unsigned b0, unsigned b1) {
    asm("mma.sync.aligned.m16n8k8.row.col.f32.tf32.tf32.f32 "
        "{%0,%1,%2,%3}, {%4,%5,%6,%7}, {%8,%9}, {%0,%1,%2,%3};"
        : "+f"(c[0]), "+f"(c[1]), "+f"(c[2]), "+f"(c[3])
        : "r"(a0), "r"(a1), "r"(a2), "r"(a3), "r"(b0), "r"(b1));
}
__device__ __forceinline__ void ldsm4(unsigned &r0, unsigned &r1,
                                      unsigned &r2, unsigned &r3, unsigned addr) {
    asm volatile("ldmatrix.sync.aligned.m8n8.x4.shared.b16 {%0,%1,%2,%3}, [%4];"
                 : "=r"(r0), "=r"(r1), "=r"(r2), "=r"(r3) : "r"(addr));
}

// ---------------------------------------------------------------------------
// Kernel 0: transpose + tf32-round weights into g_Wt[n][k].
// grid (ND/32, 64/32, 3), block (32, 8).
// ---------------------------------------------------------------------------
__global__ void wt_kernel(const float* __restrict__ Wq,
                          const float* __restrict__ Wk,
                          const float* __restrict__ Wv)
{
    __shared__ float tb[32][33];
    const int z = blockIdx.z;
    const float* __restrict__ W = (z == 0) ? Wq : (z == 1) ? Wk : Wv;
    const int k0 = blockIdx.x * 32, n0 = blockIdx.y * 32;
    const int tx = threadIdx.x, ty = threadIdx.y;
#pragma unroll
    for (int i = 0; i < 4; ++i)
        tb[ty + i * 8][tx] = W[(size_t)(k0 + ty + i * 8) * NH + n0 + tx];
    __syncthreads();
#pragma unroll
    for (int i = 0; i < 4; ++i)
        g_Wt[(size_t)(z * NH + n0 + ty + i * 8) * ND + k0 + tx] =
            __uint_as_float(f2tf(tb[tx][ty + i * 8]));
}

// ---------------------------------------------------------------------------
// Kernel 1: QKV projection, one z-slice per blockIdx.y.
// Block: 256 threads / 8 warps, tile 128m x 64n, k-stage 32.
// Warp w owns m rows [w*16, w*16+16), all 8 n-tiles. acc = 32 regs/thread.
// All fragments via ldmatrix from smem (X tf32-converted on store; Wt is
// pre-rounded tf32 bits, plain copy).
// ---------------------------------------------------------------------------
__global__ __launch_bounds__(256, 3) void proj_kernel(const float* __restrict__ X)
{
    __shared__ float Xs[128 * PXS];       // 18.4 KB
    __shared__ float Ws[64 * PWS];        //  9.2 KB

    const int z    = blockIdx.y;
    float* __restrict__ Out = (z == 0) ? g_Q : (z == 1) ? g_K : g_V;
    const float* __restrict__ Wz = g_Wt + (size_t)z * NH * ND;

    const int row0 = blockIdx.x * 128;
    const int tid  = threadIdx.x;
    const int wrp  = tid >> 5;
    const int lane = tid & 31;
    const int g    = lane >> 2;
    const int t    = lane & 3;
    const int w16  = wrp * 16;

    float acc[8][4];
#pragma unroll
    for (int nt = 0; nt < 8; ++nt)
#pragma unroll
        for (int r = 0; r < 4; ++r) acc[nt][r] = 0.0f;

    const unsigned smbX = (unsigned)__cvta_generic_to_shared(Xs);
    const unsigned smbW = (unsigned)__cvta_generic_to_shared(Ws);
    const int rowA = w16 + (lane & 15);
    const int colA = (lane >> 4) * 4;
    const unsigned aX = smbX + (unsigned)((rowA * PXS + colA) * 4);
    const int rowB = (lane & 7) | ((lane >> 1) & 8);
    const int colB = ((lane >> 3) & 1) * 4;
    const unsigned bW = smbW + (unsigned)((rowB * PWS + colB) * 4);

    const int xr = tid >> 1;              // 0..127
    const int xc = (tid & 1) * 16;        // 0 or 16

    for (int kk = 0; kk < ND; kk += 32) {
        // X tile 128x32, tf32-rounded: 256 threads x 4 float4
#pragma unroll
        for (int u = 0; u < 4; ++u) {
            float4 v = *reinterpret_cast<const float4*>(
                X + (size_t)(row0 + xr) * ND + kk + xc + u * 4);
            *reinterpret_cast<uint4*>(&Xs[xr * PXS + xc + u * 4]) = f4tf(v);
        }
        // W slice tile 64x32: 512 float4, 2 iterations
#pragma unroll
        for (int it = 0; it < 2; ++it) {
            const int fi = it * 256 + tid;
            const int n  = fi >> 3;
            const int c4 = (fi & 7) * 4;
            *reinterpret_cast<float4*>(&Ws[n * PWS + c4]) =
                *reinterpret_cast<const float4*>(&Wz[(size_t)n * ND + kk + c4]);
        }
        __syncthreads();

#pragma unroll
        for (int dc = 0; dc < 4; ++dc) {
            unsigned a0, a1, a2, a3;
            ldsm4(a0, a1, a2, a3, aX + dc * 32);
#pragma unroll
            for (int p = 0; p < 4; ++p) {
                unsigned b0, b1, b2, b3;
                ldsm4(b0, b1, b2, b3, bW + p * (16 * PWS * 4) + dc * 32);
                mma8(acc[2 * p],     a0, a1, a2, a3, b0, b1);
                mma8(acc[2 * p + 1], a0, a1, a2, a3, b2, b3);
            }
        }
        __syncthreads();
    }

#pragma unroll
    for (int nt = 0; nt < 8; ++nt) {
        const int col = nt * 8 + 2 * t;
        const int rA  = row0 + w16 + g;
        *reinterpret_cast<float2*>(Out + (size_t)rA * NH + col) =
            make_float2(acc[nt][0], acc[nt][1]);
        *reinterpret_cast<float2*>(Out + (size_t)(rA + 8) * NH + col) =
            make_float2(acc[nt][2], acc[nt][3]);
    }
}

// ---------------------------------------------------------------------------
// Kernel 2: causal flash attention, tf32 mma + ldmatrix + split-K x2.
// (byte-identical to the proven R8 version)
// ---------------------------------------------------------------------------
__global__ __launch_bounds__(128, 3) void attn_kernel()
{
    extern __shared__ float sm[];
    float* __restrict__ Qs = sm;                 // [64][68]
    float* __restrict__ Ks = sm + 64 * SKA;      // [64][68]
    float* __restrict__ Ps = sm + 2 * 64 * SKA;  // [64][68]
    float* __restrict__ Vt = sm + 3 * 64 * SKA;  // [64][68] V transposed [h][k]

    const int b    = blockIdx.y;
    const int qt   = (NQT - 1) - blockIdx.x;
    const int half = blockIdx.z;
    const int q0   = qt * 64;
    const int tid  = threadIdx.x;
    const int wrp  = tid >> 5;
    const int lane = tid & 31;
    const int g    = lane >> 2;
    const int t    = lane & 3;
    const int w16  = wrp * 16;

    const int T  = qt + 1;
    const int h0 = (T + 1) >> 1;
    const int tb = half ? h0 : 0;
    const int te = half ? T  : h0;

    const float* __restrict__ Qb = g_Q + (size_t)b * NS * NH;
    const float* __restrict__ Kb = g_K + (size_t)b * NS * NH;
    const float* __restrict__ Vb = g_V + (size_t)b * NS * NH;

    const unsigned smb = (unsigned)__cvta_generic_to_shared(sm);
    const int rowA = w16 + (lane & 15);
    const int colA = (lane >> 4) * 4;
    const unsigned aQ = smb + (unsigned)((rowA * SKA + colA) * 4);
    const unsigned aP = aQ + 2u * 64 * SKA * 4;
    const int rowB = (lane & 7) | ((lane >> 1) & 8);
    const int colB = ((lane >> 3) & 1) * 4;
    const unsigned bK = smb + 1u * 64 * SKA * 4 + (unsigned)((rowB * SKA + colB) * 4);
    const unsigned bV = smb + 3u * 64 * SKA * 4 + (unsigned)((rowB * SKA + colB) * 4);

    {
        const int r = tid >> 1;
        const int c = (tid & 1) * 32;
        const float4* qp = reinterpret_cast<const float4*>(
            Qb + (size_t)(q0 + r) * NH + c);
#pragma unroll
        for (int u = 0; u < 8; ++u)
            *reinterpret_cast<uint4*>(&Qs[r * SKA + c + u * 4]) = f4tf(qp[u]);
    }

    float o[8][4];
#pragma unroll
    for (int nt = 0; nt < 8; ++nt)
#pragma unroll
        for (int r = 0; r < 4; ++r) o[nt][r] = 0.0f;
    float mA = -1e30f, mB = -1e30f;
    float lA = 0.0f,   lB = 0.0f;

    for (int kt = tb; kt < te; ++kt) {
        const int k0 = kt * 64;

        __syncthreads();
        {
            const int r = tid >> 1;
            const int c = (tid & 1) * 32;
            const float4* kp = reinterpret_cast<const float4*>(
                Kb + (size_t)(k0 + r) * NH + c);
#pragma unroll
            for (int u = 0; u < 8; ++u)
                *reinterpret_cast<uint4*>(&Ks[r * SKA + c + u * 4]) = f4tf(kp[u]);
        }
        {
            const int rv = tid & 63;
            const int hb = (tid >> 6) * 32;
            const float4* vp = reinterpret_cast<const float4*>(
                Vb + (size_t)(k0 + rv) * NH + hb);
#pragma unroll
            for (int u = 0; u < 8; ++u) {
                float4 v = vp[u];
                const int h = hb + u * 4;
                Vt[(h + 0) * SKA + rv] = __uint_as_float(f2tf(v.x));
                Vt[(h + 1) * SKA + rv] = __uint_as_float(f2tf(v.y));
                Vt[(h + 2) * SKA + rv] = __uint_as_float(f2tf(v.z));
                Vt[(h + 3) * SKA + rv] = __uint_as_float(f2tf(v.w));
            }
        }
        __syncthreads();

        float s[8][4];
#pragma unroll
        for (int nt = 0; nt < 8; ++nt)
#pragma unroll
            for (int r = 0; r < 4; ++r) s[nt][r] = 0.0f;

#pragma unroll
        for (int dc = 0; dc < 8; ++dc) {
            unsigned a0, a1, a2, a3;
            ldsm4(a0, a1, a2, a3, aQ + dc * 32);
#pragma unroll
            for (int p = 0; p < 4; ++p) {
                unsigned b0, b1, b2, b3;
                ldsm4(b0, b1, b2, b3, bK + p * (16 * SKA * 4) + dc * 32);
                mma8(s[2 * p],     a0, a1, a2, a3, b0, b1);
                mma8(s[2 * p + 1], a0, a1, a2, a3, b2, b3);
            }
        }

        if (kt == qt) {
            const int rA = w16 + g, rB = w16 + g + 8;
#pragma unroll
            for (int nt = 0; nt < 8; ++nt) {
                const int c0 = nt * 8 + 2 * t, c1 = c0 + 1;
                s[nt][0] = (c0 <= rA) ? s[nt][0] * 0.125f : -1e30f;
                s[nt][1] = (c1 <= rA) ? s[nt][1] * 0.125f : -1e30f;
                s[nt][2] = (c0 <= rB) ? s[nt][2] * 0.125f : -1e30f;
                s[nt][3] = (c1 <= rB) ? s[nt][3] * 0.125f : -1e30f;
            }
        } else {
#pragma unroll
            for (int nt = 0; nt < 8; ++nt)
#pragma unroll
                for (int r = 0; r < 4; ++r) s[nt][r] *= 0.125f;
        }

        float cmA = -1e30f, cmB = -1e30f;
#pragma unroll
        for (int nt = 0; nt < 8; ++nt) {
            cmA = fmaxf(cmA, fmaxf(s[nt][0], s[nt][1]));
            cmB = fmaxf(cmB, fmaxf(s[nt][2], s[nt][3]));
        }
        cmA = fmaxf(cmA, __shfl_xor_sync(0xffffffffu, cmA, 1));
        cmA = fmaxf(cmA, __shfl_xor_sync(0xffffffffu, cmA, 2));
        cmB = fmaxf(cmB, __shfl_xor_sync(0xffffffffu, cmB, 1));
        cmB = fmaxf(cmB, __shfl_xor_sync(0xffffffffu, cmB, 2));

        const float mnA = fmaxf(mA, cmA);
        const float mnB = fmaxf(mB, cmB);
        const float cA  = __expf(mA - mnA);
        const float cB  = __expf(mB - mnB);
        mA = mnA; mB = mnB;
        lA *= cA; lB *= cB;
#pragma unroll
        for (int nt = 0; nt < 8; ++nt) {
            o[nt][0] *= cA; o[nt][1] *= cA;
            o[nt][2] *= cB; o[nt][3] *= cB;
        }
#pragma unroll
        for (int nt = 0; nt < 8; ++nt) {
            s[nt][0] = __expf(s[nt][0] - mnA);
            s[nt][1] = __expf(s[nt][1] - mnA);
            s[nt][2] = __expf(s[nt][2] - mnB);
            s[nt][3] = __expf(s[nt][3] - mnB);
            lA += s[nt][0] + s[nt][1];
            lB += s[nt][2] + s[nt][3];
        }

#pragma unroll
        for (int nt = 0; nt < 8; ++nt) {
            *reinterpret_cast<uint2*>(&Ps[(w16 + g) * SKA + nt * 8 + 2 * t]) =
                make_uint2(f2tf(s[nt][0]), f2tf(s[nt][1]));
            *reinterpret_cast<uint2*>(&Ps[(w16 + g + 8) * SKA + nt * 8 + 2 * t]) =
                make_uint2(f2tf(s[nt][2]), f2tf(s[nt][3]));
        }
        __syncwarp();

#pragma unroll
        for (int kc = 0; kc < 8; ++kc) {
            unsigned a0, a1, a2, a3;
            ldsm4(a0, a1, a2, a3, aP + kc * 32);
#pragma unroll
            for (int p = 0; p < 4; ++p) {
                unsigned b0, b1, b2, b3;
                ldsm4(b0, b1, b2, b3, bV + p * (16 * SKA * 4) + kc * 32);
                mma8(o[2 * p],     a0, a1, a2, a3, b0, b1);
                mma8(o[2 * p + 1], a0, a1, a2, a3, b2, b3);
            }
        }
        __syncwarp();
    }

    lA += __shfl_xor_sync(0xffffffffu, lA, 1);
    lA += __shfl_xor_sync(0xffffffffu, lA, 2);
    lB += __shfl_xor_sync(0xffffffffu, lB, 1);
    lB += __shfl_xor_sync(0xffffffffu, lB, 2);

    const size_t slot = ((size_t)half * NB + b) * NQT + qt;
    float* op = g_Op + slot * 64 * 64;
#pragma unroll
    for (int nt = 0; nt < 8; ++nt) {
        *reinterpret_cast<float2*>(op + (w16 + g) * 64 + nt * 8 + 2 * t) =
            make_float2(o[nt][0], o[nt][1]);
        *reinterpret_cast<float2*>(op + (w16 + g + 8) * 64 + nt * 8 + 2 * t) =
            make_float2(o[nt][2], o[nt][3]);
    }
    if (t == 0) {
        g_M[slot * 64 + w16 + g]     = mA;
        g_M[slot * 64 + w16 + g + 8] = mB;
        g_L[slot * 64 + w16 + g]     = lA;
        g_L[slot * 64 + w16 + g + 8] = lB;
    }
}

// ---------------------------------------------------------------------------
// Kernel 3: merge split-K partials. grid (32, NB), 256 threads.
// ---------------------------------------------------------------------------
__global__ __launch_bounds__(256) void merge_kernel(float* __restrict__ out)
{
    const int qt  = blockIdx.x;
    const int b   = blockIdx.y;
    const int tid = threadIdx.x;
    const int r   = tid >> 2;
    const int cs  = (tid & 3) * 16;

    const size_t s0 = ((size_t)0 * NB + b) * NQT + qt;
    const size_t s1 = ((size_t)1 * NB + b) * NQT + qt;

    const float m0 = g_M[s0 * 64 + r];
    const float m1 = g_M[s1 * 64 + r];
    const float l0 = g_L[s0 * 64 + r];
    const float l1 = g_L[s1 * 64 + r];

    const float M  = fmaxf(m0, m1);
    float f0 = __expf(m0 - M);
    float f1 = __expf(m1 - M);
    const float inv = 1.0f / (l0 * f0 + l1 * f1);
    f0 *= inv; f1 *= inv;

    const float4* p0 = reinterpret_cast<const float4*>(g_Op + s0 * 4096 + r * 64 + cs);
    const float4* p1 = reinterpret_cast<const float4*>(g_Op + s1 * 4096 + r * 64 + cs);
    float4* po = reinterpret_cast<float4*>(
        out + ((size_t)b * NS + qt * 64 + r) * NH + cs);

#pragma unroll
    for (int u = 0; u < 4; ++u) {
        float4 a = p0[u], c = p1[u];
        po[u] = make_float4(a.x * f0 + c.x * f1, a.y * f0 + c.y * f1,
                            a.z * f0 + c.z * f1, a.w * f0 + c.w * f1);
    }
}

// ---------------------------------------------------------------------------
extern "C" void kernel_launch(void* const* d_in, const int* in_sizes, int n_in,
                              void* d_out, int out_size)
{
    const float* X  = (const float*)d_in[0];
    const float* Wq = (const float*)d_in[1];
    const float* Wk = (const float*)d_in[2];
    const float* Wv = (const float*)d_in[3];
    float* out = (float*)d_out;

    const int attn_smem = 4 * 64 * SKA * (int)sizeof(float);   // 69632 B
    cudaFuncSetAttribute(attn_kernel,
                         cudaFuncAttributeMaxDynamicSharedMemorySize, attn_smem);

    wt_kernel<<<dim3(ND / 32, NH / 32, 3), dim3(32, 8)>>>(Wq, Wk, Wv);
    proj_kernel<<<dim3((NB * NS) / 128, 3), 256>>>(X);
    attn_kernel<<<dim3(NQT, NB, 2), 128, attn_smem>>>();
    merge_kernel<<<dim3(NQT, NB), 256>>>(out);
}

// round 11
// speedup vs baseline: 1.1476x; 1.1476x over previous
#include <cuda_runtime.h>

#define NB 8
#define NS 2048
#define ND 768
#define NH 64
#define NQT 32            // q-tiles of 64
#define NSPL 4            // split-K factor
#define SKA 68            // attn smem stride (floats), 68 % 32 == 4 -> conflict-free LDSM

__device__ float g_Q[NB * NS * NH];
__device__ float g_K[NB * NS * NH];
__device__ float g_V[NB * NS * NH];

// split-K partials: [split][b][qt] -> 64x64 unnormalized O, plus per-row m,l
__device__ float g_Op[NSPL * NB * NQT * 64 * 64];
__device__ float g_M[NSPL * NB * NQT * 64];
__device__ float g_L[NSPL * NB * NQT * 64];

// ---------------------------------------------------------------------------
// helpers
// ---------------------------------------------------------------------------
__device__ __forceinline__ unsigned f2tf(float f) {
    unsigned u;
    asm("cvt.rna.tf32.f32 %0, %1;" : "=r"(u) : "f"(f));
    return u;
}
__device__ __forceinline__ uint4 f4tf(float4 v) {
    uint4 r;
    r.x = f2tf(v.x); r.y = f2tf(v.y); r.z = f2tf(v.z); r.w = f2tf(v.w);
    return r;
}
__device__ __forceinline__ void mma8(float c[4],
                                     unsigned a0, unsigned a1, unsigned a2, unsigned a3,
                                     unsigned b0, unsigned b1) {
    asm("mma.sync.aligned.m16n8k8.row.col.f32.tf32.tf32.f32 "
        "{%0,%1,%2,%3}, {%4,%5,%6,%7}, {%8,%9}, {%0,%1,%2,%3};"
        : "+f"(c[0]), "+f"(c[1]), "+f"(c[2]), "+f"(c[3])
        : "r"(a0), "r"(a1), "r"(a2), "r"(a3), "r"(b0), "r"(b1));
}
__device__ __forceinline__ void ldsm4(unsigned &r0, unsigned &r1,
                                      unsigned &r2, unsigned &r3, unsigned addr) {
    asm volatile("ldmatrix.sync.aligned.m8n8.x4.shared.b16 {%0,%1,%2,%3}, [%4];"
                 : "=r"(r0), "=r"(r1), "=r"(r2), "=r"(r3) : "r"(addr));
}

// ---------------------------------------------------------------------------
// Kernel 1: QKV projection via tf32 mma (exact R8 version — proven 46.8 us).
// ---------------------------------------------------------------------------
#define XS_S 36
#define WS_S 72

__global__ __launch_bounds__(128, 3) void proj_kernel(
    const float* __restrict__ X,
    const float* __restrict__ Wq,
    const float* __restrict__ Wk,
    const float* __restrict__ Wv)
{
    const int z = blockIdx.z;
    const float* __restrict__ W   = (z == 0) ? Wq : (z == 1) ? Wk : Wv;
    float* __restrict__       Out = (z == 0) ? g_Q : (z == 1) ? g_K : g_V;

    __shared__ float Xs[128 * XS_S];
    __shared__ float Ws[32 * WS_S];

    const int row0 = blockIdx.x * 128;
    const int tid  = threadIdx.x;
    const int wrp  = tid >> 5;
    const int lane = tid & 31;
    const int g    = lane >> 2;
    const int t    = lane & 3;
    const int mrow = wrp * 32;

    float acc[2][8][4];
#pragma unroll
    for (int mt = 0; mt < 2; ++mt)
#pragma unroll
        for (int nt = 0; nt < 8; ++nt)
#pragma unroll
            for (int r = 0; r < 4; ++r) acc[mt][nt][r] = 0.0f;

    const int xr = tid >> 3;
    const int xc = (tid & 7) * 4;
    const int wr = tid >> 4;
    const int wc = (tid & 15) * 4;

    for (int kk = 0; kk < ND; kk += 32) {
#pragma unroll
        for (int it = 0; it < 8; ++it) {
            const int r = xr + it * 16;
            float4 v = *reinterpret_cast<const float4*>(
                X + (size_t)(row0 + r) * ND + kk + xc);
            *reinterpret_cast<uint4*>(&Xs[r * XS_S + xc]) = f4tf(v);
        }
#pragma unroll
        for (int it = 0; it < 4; ++it) {
            const int r = wr + it * 8;
            float4 v = *reinterpret_cast<const float4*>(
                W + (size_t)(kk + r) * NH + wc);
            *reinterpret_cast<uint4*>(&Ws[r * WS_S + wc]) = f4tf(v);
        }
        __syncthreads();

#pragma unroll
        for (int dc = 0; dc < 4; ++dc) {
            unsigned a[2][4];
#pragma unroll
            for (int mt = 0; mt < 2; ++mt) {
                const int rb = mrow + mt * 16;
                a[mt][0] = __float_as_uint(Xs[(rb + g)     * XS_S + dc * 8 + t]);
                a[mt][1] = __float_as_uint(Xs[(rb + g + 8) * XS_S + dc * 8 + t]);
                a[mt][2] = __float_as_uint(Xs[(rb + g)     * XS_S + dc * 8 + t + 4]);
                a[mt][3] = __float_as_uint(Xs[(rb + g + 8) * XS_S + dc * 8 + t + 4]);
            }
#pragma unroll
            for (int nt = 0; nt < 8; ++nt) {
                unsigned b0 = __float_as_uint(Ws[(dc * 8 + t)     * WS_S + nt * 8 + g]);
                unsigned b1 = __float_as_uint(Ws[(dc * 8 + t + 4) * WS_S + nt * 8 + g]);
                mma8(acc[0][nt], a[0][0], a[0][1], a[0][2], a[0][3], b0, b1);
                mma8(acc[1][nt], a[1][0], a[1][1], a[1][2], a[1][3], b0, b1);
            }
        }
        __syncthreads();
    }

#pragma unroll
    for (int mt = 0; mt < 2; ++mt) {
        const int rb = row0 + mrow + mt * 16;
#pragma unroll
        for (int nt = 0; nt < 8; ++nt) {
            *reinterpret_cast<float2*>(
                Out + (size_t)(rb + g) * NH + nt * 8 + 2 * t) =
                make_float2(acc[mt][nt][0], acc[mt][nt][1]);
            *reinterpret_cast<float2*>(
                Out + (size_t)(rb + g + 8) * NH + nt * 8 + 2 * t) =
                make_float2(acc[mt][nt][2], acc[mt][nt][3]);
        }
    }
}

// ---------------------------------------------------------------------------
// Kernel 2: causal flash attention, tf32 mma + ldmatrix + split-K x4.
// Identical to R8 except the k-tile range is a quarter: [(T*s)/4, (T*(s+1))/4).
// Empty quarters store m=-1e30, l=0, O=0 (zero weight in merge).
// ---------------------------------------------------------------------------
__global__ __launch_bounds__(128, 3) void attn_kernel()
{
    extern __shared__ float sm[];
    float* __restrict__ Qs = sm;                 // [64][68]
    float* __restrict__ Ks = sm + 64 * SKA;      // [64][68]
    float* __restrict__ Ps = sm + 2 * 64 * SKA;  // [64][68]
    float* __restrict__ Vt = sm + 3 * 64 * SKA;  // [64][68] V transposed [h][k]

    const int b    = blockIdx.y;
    const int qt   = (NQT - 1) - blockIdx.x;
    const int spl  = blockIdx.z;
    const int q0   = qt * 64;
    const int tid  = threadIdx.x;
    const int wrp  = tid >> 5;
    const int lane = tid & 31;
    const int g    = lane >> 2;
    const int t    = lane & 3;
    const int w16  = wrp * 16;

    const int T  = qt + 1;
    const int tb = (T * spl) >> 2;
    const int te = (T * (spl + 1)) >> 2;

    const float* __restrict__ Qb = g_Q + (size_t)b * NS * NH;
    const float* __restrict__ Kb = g_K + (size_t)b * NS * NH;
    const float* __restrict__ Vb = g_V + (size_t)b * NS * NH;

    const unsigned smb = (unsigned)__cvta_generic_to_shared(sm);
    const int rowA = w16 + (lane & 15);
    const int colA = (lane >> 4) * 4;
    const unsigned aQ = smb + (unsigned)((rowA * SKA + colA) * 4);
    const unsigned aP = aQ + 2u * 64 * SKA * 4;
    const int rowB = (lane & 7) | ((lane >> 1) & 8);
    const int colB = ((lane >> 3) & 1) * 4;
    const unsigned bK = smb + 1u * 64 * SKA * 4 + (unsigned)((rowB * SKA + colB) * 4);
    const unsigned bV = smb + 3u * 64 * SKA * 4 + (unsigned)((rowB * SKA + colB) * 4);

    if (tb < te) {   // non-empty range: load Q
        const int r = tid >> 1;
        const int c = (tid & 1) * 32;
        const float4* qp = reinterpret_cast<const float4*>(
            Qb + (size_t)(q0 + r) * NH + c);
#pragma unroll
        for (int u = 0; u < 8; ++u)
            *reinterpret_cast<uint4*>(&Qs[r * SKA + c + u * 4]) = f4tf(qp[u]);
    }

    float o[8][4];
#pragma unroll
    for (int nt = 0; nt < 8; ++nt)
#pragma unroll
        for (int r = 0; r < 4; ++r) o[nt][r] = 0.0f;
    float mA = -1e30f, mB = -1e30f;
    float lA = 0.0f,   lB = 0.0f;

    for (int kt = tb; kt < te; ++kt) {
        const int k0 = kt * 64;

        __syncthreads();
        {
            const int r = tid >> 1;
            const int c = (tid & 1) * 32;
            const float4* kp = reinterpret_cast<const float4*>(
                Kb + (size_t)(k0 + r) * NH + c);
#pragma unroll
            for (int u = 0; u < 8; ++u)
                *reinterpret_cast<uint4*>(&Ks[r * SKA + c + u * 4]) = f4tf(kp[u]);
        }
        {
            const int rv = tid & 63;
            const int hb = (tid >> 6) * 32;
            const float4* vp = reinterpret_cast<const float4*>(
                Vb + (size_t)(k0 + rv) * NH + hb);
#pragma unroll
            for (int u = 0; u < 8; ++u) {
                float4 v = vp[u];
                const int h = hb + u * 4;
                Vt[(h + 0) * SKA + rv] = __uint_as_float(f2tf(v.x));
                Vt[(h + 1) * SKA + rv] = __uint_as_float(f2tf(v.y));
                Vt[(h + 2) * SKA + rv] = __uint_as_float(f2tf(v.z));
                Vt[(h + 3) * SKA + rv] = __uint_as_float(f2tf(v.w));
            }
        }
        __syncthreads();

        float s[8][4];
#pragma unroll
        for (int nt = 0; nt < 8; ++nt)
#pragma unroll
            for (int r = 0; r < 4; ++r) s[nt][r] = 0.0f;

#pragma unroll
        for (int dc = 0; dc < 8; ++dc) {
            unsigned a0, a1, a2, a3;
            ldsm4(a0, a1, a2, a3, aQ + dc * 32);
#pragma unroll
            for (int p = 0; p < 4; ++p) {
                unsigned b0, b1, b2, b3;
                ldsm4(b0, b1, b2, b3, bK + p * (16 * SKA * 4) + dc * 32);
                mma8(s[2 * p],     a0, a1, a2, a3, b0, b1);
                mma8(s[2 * p + 1], a0, a1, a2, a3, b2, b3);
            }
        }

        if (kt == qt) {
            const int rA = w16 + g, rB = w16 + g + 8;
#pragma unroll
            for (int nt = 0; nt < 8; ++nt) {
                const int c0 = nt * 8 + 2 * t, c1 = c0 + 1;
                s[nt][0] = (c0 <= rA) ? s[nt][0] * 0.125f : -1e30f;
                s[nt][1] = (c1 <= rA) ? s[nt][1] * 0.125f : -1e30f;
                s[nt][2] = (c0 <= rB) ? s[nt][2] * 0.125f : -1e30f;
                s[nt][3] = (c1 <= rB) ? s[nt][3] * 0.125f : -1e30f;
            }
        } else {
#pragma unroll
            for (int nt = 0; nt < 8; ++nt)
#pragma unroll
                for (int r = 0; r < 4; ++r) s[nt][r] *= 0.125f;
        }

        float cmA = -1e30f, cmB = -1e30f;
#pragma unroll
        for (int nt = 0; nt < 8; ++nt) {
            cmA = fmaxf(cmA, fmaxf(s[nt][0], s[nt][1]));
            cmB = fmaxf(cmB, fmaxf(s[nt][2], s[nt][3]));
        }
        cmA = fmaxf(cmA, __shfl_xor_sync(0xffffffffu, cmA, 1));
        cmA = fmaxf(cmA, __shfl_xor_sync(0xffffffffu, cmA, 2));
        cmB = fmaxf(cmB, __shfl_xor_sync(0xffffffffu, cmB, 1));
        cmB = fmaxf(cmB, __shfl_xor_sync(0xffffffffu, cmB, 2));

        const float mnA = fmaxf(mA, cmA);
        const float mnB = fmaxf(mB, cmB);
        const float cA  = __expf(mA - mnA);
        const float cB  = __expf(mB - mnB);
        mA = mnA; mB = mnB;
        lA *= cA; lB *= cB;
#pragma unroll
        for (int nt = 0; nt < 8; ++nt) {
            o[nt][0] *= cA; o[nt][1] *= cA;
            o[nt][2] *= cB; o[nt][3] *= cB;
        }
#pragma unroll
        for (int nt = 0; nt < 8; ++nt) {
            s[nt][0] = __expf(s[nt][0] - mnA);
            s[nt][1] = __expf(s[nt][1] - mnA);
            s[nt][2] = __expf(s[nt][2] - mnB);
            s[nt][3] = __expf(s[nt][3] - mnB);
            lA += s[nt][0] + s[nt][1];
            lB += s[nt][2] + s[nt][3];
        }

#pragma unroll
        for (int nt = 0; nt < 8; ++nt) {
            *reinterpret_cast<uint2*>(&Ps[(w16 + g) * SKA + nt * 8 + 2 * t]) =
                make_uint2(f2tf(s[nt][0]), f2tf(s[nt][1]));
            *reinterpret_cast<uint2*>(&Ps[(w16 + g + 8) * SKA + nt * 8 + 2 * t]) =
                make_uint2(f2tf(s[nt][2]), f2tf(s[nt][3]));
        }
        __syncwarp();

#pragma unroll
        for (int kc = 0; kc < 8; ++kc) {
            unsigned a0, a1, a2, a3;
            ldsm4(a0, a1, a2, a3, aP + kc * 32);
#pragma unroll
            for (int p = 0; p < 4; ++p) {
                unsigned b0, b1, b2, b3;
                ldsm4(b0, b1, b2, b3, bV + p * (16 * SKA * 4) + kc * 32);
                mma8(o[2 * p],     a0, a1, a2, a3, b0, b1);
                mma8(o[2 * p + 1], a0, a1, a2, a3, b2, b3);
            }
        }
        __syncwarp();
    }

    lA += __shfl_xor_sync(0xffffffffu, lA, 1);
    lA += __shfl_xor_sync(0xffffffffu, lA, 2);
    lB += __shfl_xor_sync(0xffffffffu, lB, 1);
    lB += __shfl_xor_sync(0xffffffffu, lB, 2);

    const size_t slot = ((size_t)spl * NB + b) * NQT + qt;
    float* op = g_Op + slot * 64 * 64;
#pragma unroll
    for (int nt = 0; nt < 8; ++nt) {
        *reinterpret_cast<float2*>(op + (w16 + g) * 64 + nt * 8 + 2 * t) =
            make_float2(o[nt][0], o[nt][1]);
        *reinterpret_cast<float2*>(op + (w16 + g + 8) * 64 + nt * 8 + 2 * t) =
            make_float2(o[nt][2], o[nt][3]);
    }
    if (t == 0) {
        g_M[slot * 64 + w16 + g]     = mA;
        g_M[slot * 64 + w16 + g + 8] = mB;
        g_L[slot * 64 + w16 + g]     = lA;
        g_L[slot * 64 + w16 + g + 8] = lB;
    }
}

// ---------------------------------------------------------------------------
// Kernel 3: merge NSPL split-K partials. grid (32, NB), 256 threads.
// ---------------------------------------------------------------------------
__global__ __launch_bounds__(256) void merge_kernel(float* __restrict__ out)
{
    const int qt  = blockIdx.x;
    const int b   = blockIdx.y;
    const int tid = threadIdx.x;
    const int r   = tid >> 2;
    const int cs  = (tid & 3) * 16;

    size_t slot[NSPL];
    float  m[NSPL], l[NSPL];
    float  M = -1e30f;
#pragma unroll
    for (int s = 0; s < NSPL; ++s) {
        slot[s] = ((size_t)s * NB + b) * NQT + qt;
        m[s] = g_M[slot[s] * 64 + r];
        l[s] = g_L[slot[s] * 64 + r];
        M = fmaxf(M, m[s]);
    }
    float f[NSPL], den = 0.0f;
#pragma unroll
    for (int s = 0; s < NSPL; ++s) {
        f[s] = __expf(m[s] - M);     // empty split: exp(-1e30 - M) = 0
        den += l[s] * f[s];
    }
    const float inv = 1.0f / den;
#pragma unroll
    for (int s = 0; s < NSPL; ++s) f[s] *= inv;

    float4* po = reinterpret_cast<float4*>(
        out + ((size_t)b * NS + qt * 64 + r) * NH + cs);

#pragma unroll
    for (int u = 0; u < 4; ++u) {
        float4 acc = make_float4(0.f, 0.f, 0.f, 0.f);
#pragma unroll
        for (int s = 0; s < NSPL; ++s) {
            float4 v = *reinterpret_cast<const float4*>(
                g_Op + slot[s] * 4096 + r * 64 + cs + u * 4);
            acc.x += v.x * f[s]; acc.y += v.y * f[s];
            acc.z += v.z * f[s]; acc.w += v.w * f[s];
        }
        po[u] = acc;
    }
}

// ---------------------------------------------------------------------------
extern "C" void kernel_launch(void* const* d_in, const int* in_sizes, int n_in,
                              void* d_out, int out_size)
{
    const float* X  = (const float*)d_in[0];
    const float* Wq = (const float*)d_in[1];
    const float* Wk = (const float*)d_in[2];
    const float* Wv = (const float*)d_in[3];
    float* out = (float*)d_out;

    const int attn_smem = 4 * 64 * SKA * (int)sizeof(float);   // 69632 B
    cudaFuncSetAttribute(attn_kernel,
                         cudaFuncAttributeMaxDynamicSharedMemorySize, attn_smem);

    proj_kernel<<<dim3((NB * NS) / 128, 1, 3), 128>>>(X, Wq, Wk, Wv);
    attn_kernel<<<dim3(NQT, NB, NSPL), 128, attn_smem>>>();
    merge_kernel<<<dim3(NQT, NB), 256>>>(out);
}

// round 12
// speedup vs baseline: 1.1637x; 1.0140x over previous
#include <cuda_runtime.h>

#define NB 8
#define NS 2048
#define ND 768
#define NH 64
#define NQT 32            // q-tiles of 64
#define NSPL 4            // split-K factor
#define SKA 68            // attn smem stride (floats), 68 % 32 == 4 -> conflict-free LDSM

// g_Q, g_K: [b][n][h] tf32 bits.  g_V: [b][h][n] tf32 bits (pre-transposed).
__device__ float g_Q[NB * NS * NH];
__device__ float g_K[NB * NS * NH];
__device__ float g_V[NB * NH * NS];

// split-K partials: [split][b][qt] -> 64x64 unnormalized O, plus per-row m,l
__device__ float g_Op[NSPL * NB * NQT * 64 * 64];
__device__ float g_M[NSPL * NB * NQT * 64];
__device__ float g_L[NSPL * NB * NQT * 64];

// ---------------------------------------------------------------------------
// helpers
// ---------------------------------------------------------------------------
__device__ __forceinline__ unsigned f2tf(float f) {
    unsigned u;
    asm("cvt.rna.tf32.f32 %0, %1;" : "=r"(u) : "f"(f));
    return u;
}
__device__ __forceinline__ uint4 f4tf(float4 v) {
    uint4 r;
    r.x = f2tf(v.x); r.y = f2tf(v.y); r.z = f2tf(v.z); r.w = f2tf(v.w);
    return r;
}
__device__ __forceinline__ void mma8(float c[4],
                                     unsigned a0, unsigned a1, unsigned a2, unsigned a3,
                                     unsigned b0, unsigned b1) {
    asm("mma.sync.aligned.m16n8k8.row.col.f32.tf32.tf32.f32 "
        "{%0,%1,%2,%3}, {%4,%5,%6,%7}, {%8,%9}, {%0,%1,%2,%3};"
        : "+f"(c[0]), "+f"(c[1]), "+f"(c[2]), "+f"(c[3])
        : "r"(a0), "r"(a1), "r"(a2), "r"(a3), "r"(b0), "r"(b1));
}
__device__ __forceinline__ void ldsm4(unsigned &r0, unsigned &r1,
                                      unsigned &r2, unsigned &r3, unsigned addr) {
    asm volatile("ldmatrix.sync.aligned.m8n8.x4.shared.b16 {%0,%1,%2,%3}, [%4];"
                 : "=r"(r0), "=r"(r1), "=r"(r2), "=r"(r3) : "r"(addr));
}

// ---------------------------------------------------------------------------
// Kernel 1: QKV projection via tf32 mma (R8 mainloop). Epilogue now stores
// tf32-rounded BITS; V is additionally stored transposed: g_V[b][h][n].
// ---------------------------------------------------------------------------
#define XS_S 36
#define WS_S 72

__global__ __launch_bounds__(128, 3) void proj_kernel(
    const float* __restrict__ X,
    const float* __restrict__ Wq,
    const float* __restrict__ Wk,
    const float* __restrict__ Wv)
{
    const int z = blockIdx.z;
    const float* __restrict__ W = (z == 0) ? Wq : (z == 1) ? Wk : Wv;

    __shared__ float Xs[128 * XS_S];
    __shared__ float Ws[32 * WS_S];

    const int row0 = blockIdx.x * 128;
    const int tid  = threadIdx.x;
    const int wrp  = tid >> 5;
    const int lane = tid & 31;
    const int g    = lane >> 2;
    const int t    = lane & 3;
    const int mrow = wrp * 32;

    float acc[2][8][4];
#pragma unroll
    for (int mt = 0; mt < 2; ++mt)
#pragma unroll
        for (int nt = 0; nt < 8; ++nt)
#pragma unroll
            for (int r = 0; r < 4; ++r) acc[mt][nt][r] = 0.0f;

    const int xr = tid >> 3;
    const int xc = (tid & 7) * 4;
    const int wr = tid >> 4;
    const int wc = (tid & 15) * 4;

    for (int kk = 0; kk < ND; kk += 32) {
#pragma unroll
        for (int it = 0; it < 8; ++it) {
            const int r = xr + it * 16;
            float4 v = *reinterpret_cast<const float4*>(
                X + (size_t)(row0 + r) * ND + kk + xc);
            *reinterpret_cast<uint4*>(&Xs[r * XS_S + xc]) = f4tf(v);
        }
#pragma unroll
        for (int it = 0; it < 4; ++it) {
            const int r = wr + it * 8;
            float4 v = *reinterpret_cast<const float4*>(
                W + (size_t)(kk + r) * NH + wc);
            *reinterpret_cast<uint4*>(&Ws[r * WS_S + wc]) = f4tf(v);
        }
        __syncthreads();

#pragma unroll
        for (int dc = 0; dc < 4; ++dc) {
            unsigned a[2][4];
#pragma unroll
            for (int mt = 0; mt < 2; ++mt) {
                const int rb = mrow + mt * 16;
                a[mt][0] = __float_as_uint(Xs[(rb + g)     * XS_S + dc * 8 + t]);
                a[mt][1] = __float_as_uint(Xs[(rb + g + 8) * XS_S + dc * 8 + t]);
                a[mt][2] = __float_as_uint(Xs[(rb + g)     * XS_S + dc * 8 + t + 4]);
                a[mt][3] = __float_as_uint(Xs[(rb + g + 8) * XS_S + dc * 8 + t + 4]);
            }
#pragma unroll
            for (int nt = 0; nt < 8; ++nt) {
                unsigned b0 = __float_as_uint(Ws[(dc * 8 + t)     * WS_S + nt * 8 + g]);
                unsigned b1 = __float_as_uint(Ws[(dc * 8 + t + 4) * WS_S + nt * 8 + g]);
                mma8(acc[0][nt], a[0][0], a[0][1], a[0][2], a[0][3], b0, b1);
                mma8(acc[1][nt], a[1][0], a[1][1], a[1][2], a[1][3], b0, b1);
            }
        }
        __syncthreads();
    }

    // epilogue: tf32-round once here; Q/K natural layout, V transposed
#pragma unroll
    for (int mt = 0; mt < 2; ++mt) {
        const int rb = row0 + mrow + mt * 16;
#pragma unroll
        for (int nt = 0; nt < 8; ++nt) {
            const int col = nt * 8 + 2 * t;
            const int rA = rb + g, rB = rb + g + 8;
            const unsigned v0 = f2tf(acc[mt][nt][0]);
            const unsigned v1 = f2tf(acc[mt][nt][1]);
            const unsigned v2 = f2tf(acc[mt][nt][2]);
            const unsigned v3 = f2tf(acc[mt][nt][3]);
            if (z == 2) {
                const int bA = rA >> 11, nA = rA & 2047;
                const int bB = rB >> 11, nB = rB & 2047;
                g_V[((size_t)bA * NH + col)     * NS + nA] = __uint_as_float(v0);
                g_V[((size_t)bA * NH + col + 1) * NS + nA] = __uint_as_float(v1);
                g_V[((size_t)bB * NH + col)     * NS + nB] = __uint_as_float(v2);
                g_V[((size_t)bB * NH + col + 1) * NS + nB] = __uint_as_float(v3);
            } else {
                float* __restrict__ Out = (z == 0) ? g_Q : g_K;
                *reinterpret_cast<uint2*>(Out + (size_t)rA * NH + col) =
                    make_uint2(v0, v1);
                *reinterpret_cast<uint2*>(Out + (size_t)rB * NH + col) =
                    make_uint2(v2, v3);
            }
        }
    }
}

// ---------------------------------------------------------------------------
// Kernel 2: causal flash attention, tf32 mma + ldmatrix + split-K x4.
// All inputs pre-rounded tf32 bits; V pre-transposed -> both K and V tiles are
// plain vectorized copies. Q fragments hoisted into registers (staged via Ps).
// smem: Ks | Vt | Ps  (3 x 64 x 68 floats = 52.2 KB).
// ---------------------------------------------------------------------------
__global__ __launch_bounds__(128, 3) void attn_kernel()
{
    extern __shared__ float sm[];
    float* __restrict__ Ks = sm;                 // [64][68] K rows
    float* __restrict__ Vt = sm + 64 * SKA;      // [64][68] V^T rows [h][k]
    float* __restrict__ Ps = sm + 2 * 64 * SKA;  // [64][68] P rows / Q staging

    const int b    = blockIdx.y;
    const int qt   = (NQT - 1) - blockIdx.x;
    const int spl  = blockIdx.z;
    const int q0   = qt * 64;
    const int tid  = threadIdx.x;
    const int wrp  = tid >> 5;
    const int lane = tid & 31;
    const int g    = lane >> 2;
    const int t    = lane & 3;
    const int w16  = wrp * 16;

    const int T  = qt + 1;
    const int tb = (T * spl) >> 2;
    const int te = (T * (spl + 1)) >> 2;

    const float* __restrict__ Qb = g_Q + (size_t)b * NS * NH;
    const float* __restrict__ Kb = g_K + (size_t)b * NS * NH;
    const float* __restrict__ Vb = g_V + (size_t)b * NH * NS;

    const unsigned smb = (unsigned)__cvta_generic_to_shared(sm);
    const int rowA = w16 + (lane & 15);
    const int colA = (lane >> 4) * 4;
    const unsigned aP = smb + 2u * 64 * SKA * 4 + (unsigned)((rowA * SKA + colA) * 4);
    const int rowB = (lane & 7) | ((lane >> 1) & 8);
    const int colB = ((lane >> 3) & 1) * 4;
    const unsigned bK = smb + (unsigned)((rowB * SKA + colB) * 4);
    const unsigned bV = smb + 1u * 64 * SKA * 4 + (unsigned)((rowB * SKA + colB) * 4);

    // ---- stage Q through Ps, hoist A-fragments into registers ----
    unsigned qf[8][4];
    if (tb < te) {
        const int r = tid >> 1;
        const int c = (tid & 1) * 32;
        const float4* qp = reinterpret_cast<const float4*>(
            Qb + (size_t)(q0 + r) * NH + c);
#pragma unroll
        for (int u = 0; u < 8; ++u)
            *reinterpret_cast<float4*>(&Ps[r * SKA + c + u * 4]) = qp[u];
        __syncthreads();
#pragma unroll
        for (int dc = 0; dc < 8; ++dc)
            ldsm4(qf[dc][0], qf[dc][1], qf[dc][2], qf[dc][3], aP + dc * 32);
    }

    float o[8][4];
#pragma unroll
    for (int nt = 0; nt < 8; ++nt)
#pragma unroll
        for (int r = 0; r < 4; ++r) o[nt][r] = 0.0f;
    float mA = -1e30f, mB = -1e30f;
    float lA = 0.0f,   lB = 0.0f;

    for (int kt = tb; kt < te; ++kt) {
        const int k0 = kt * 64;

        __syncthreads();   // prev iter done reading Ks/Vt/Ps (and Q ldsm done)
        {
            const int r = tid >> 1;
            const int c = (tid & 1) * 32;
            const float4* kp = reinterpret_cast<const float4*>(
                Kb + (size_t)(k0 + r) * NH + c);
            const float4* vp = reinterpret_cast<const float4*>(
                Vb + (size_t)r * NS + k0 + c);
#pragma unroll
            for (int u = 0; u < 8; ++u) {
                *reinterpret_cast<float4*>(&Ks[r * SKA + c + u * 4]) = kp[u];
                *reinterpret_cast<float4*>(&Vt[r * SKA + c + u * 4]) = vp[u];
            }
        }
        __syncthreads();

        // ---- S = Q K^T ----
        float s[8][4];
#pragma unroll
        for (int nt = 0; nt < 8; ++nt)
#pragma unroll
            for (int r = 0; r < 4; ++r) s[nt][r] = 0.0f;

#pragma unroll
        for (int dc = 0; dc < 8; ++dc) {
#pragma unroll
            for (int p = 0; p < 4; ++p) {
                unsigned b0, b1, b2, b3;
                ldsm4(b0, b1, b2, b3, bK + p * (16 * SKA * 4) + dc * 32);
                mma8(s[2 * p],     qf[dc][0], qf[dc][1], qf[dc][2], qf[dc][3], b0, b1);
                mma8(s[2 * p + 1], qf[dc][0], qf[dc][1], qf[dc][2], qf[dc][3], b2, b3);
            }
        }

        if (kt == qt) {
            const int rA = w16 + g, rB = w16 + g + 8;
#pragma unroll
            for (int nt = 0; nt < 8; ++nt) {
                const int c0 = nt * 8 + 2 * t, c1 = c0 + 1;
                s[nt][0] = (c0 <= rA) ? s[nt][0] * 0.125f : -1e30f;
                s[nt][1] = (c1 <= rA) ? s[nt][1] * 0.125f : -1e30f;
                s[nt][2] = (c0 <= rB) ? s[nt][2] * 0.125f : -1e30f;
                s[nt][3] = (c1 <= rB) ? s[nt][3] * 0.125f : -1e30f;
            }
        } else {
#pragma unroll
            for (int nt = 0; nt < 8; ++nt)
#pragma unroll
                for (int r = 0; r < 4; ++r) s[nt][r] *= 0.125f;
        }

        // ---- online softmax ----
        float cmA = -1e30f, cmB = -1e30f;
#pragma unroll
        for (int nt = 0; nt < 8; ++nt) {
            cmA = fmaxf(cmA, fmaxf(s[nt][0], s[nt][1]));
            cmB = fmaxf(cmB, fmaxf(s[nt][2], s[nt][3]));
        }
        cmA = fmaxf(cmA, __shfl_xor_sync(0xffffffffu, cmA, 1));
        cmA = fmaxf(cmA, __shfl_xor_sync(0xffffffffu, cmA, 2));
        cmB = fmaxf(cmB, __shfl_xor_sync(0xffffffffu, cmB, 1));
        cmB = fmaxf(cmB, __shfl_xor_sync(0xffffffffu, cmB, 2));

        const float mnA = fmaxf(mA, cmA);
        const float mnB = fmaxf(mB, cmB);
        const float cA  = __expf(mA - mnA);
        const float cB  = __expf(mB - mnB);
        mA = mnA; mB = mnB;
        lA *= cA; lB *= cB;
#pragma unroll
        for (int nt = 0; nt < 8; ++nt) {
            o[nt][0] *= cA; o[nt][1] *= cA;
            o[nt][2] *= cB; o[nt][3] *= cB;
        }
#pragma unroll
        for (int nt = 0; nt < 8; ++nt) {
            s[nt][0] = __expf(s[nt][0] - mnA);
            s[nt][1] = __expf(s[nt][1] - mnA);
            s[nt][2] = __expf(s[nt][2] - mnB);
            s[nt][3] = __expf(s[nt][3] - mnB);
            lA += s[nt][0] + s[nt][1];
            lB += s[nt][2] + s[nt][3];
        }

        // ---- P -> warp-private smem rows (tf32 bits), re-fragment ----
#pragma unroll
        for (int nt = 0; nt < 8; ++nt) {
            *reinterpret_cast<uint2*>(&Ps[(w16 + g) * SKA + nt * 8 + 2 * t]) =
                make_uint2(f2tf(s[nt][0]), f2tf(s[nt][1]));
            *reinterpret_cast<uint2*>(&Ps[(w16 + g + 8) * SKA + nt * 8 + 2 * t]) =
                make_uint2(f2tf(s[nt][2]), f2tf(s[nt][3]));
        }
        __syncwarp();

        // ---- O += P V ----
#pragma unroll
        for (int kc = 0; kc < 8; ++kc) {
            unsigned a0, a1, a2, a3;
            ldsm4(a0, a1, a2, a3, aP + kc * 32);
#pragma unroll
            for (int p = 0; p < 4; ++p) {
                unsigned b0, b1, b2, b3;
                ldsm4(b0, b1, b2, b3, bV + p * (16 * SKA * 4) + kc * 32);
                mma8(o[2 * p],     a0, a1, a2, a3, b0, b1);
                mma8(o[2 * p + 1], a0, a1, a2, a3, b2, b3);
            }
        }
        __syncwarp();   // P reads done before next iteration's P writes
    }

    lA += __shfl_xor_sync(0xffffffffu, lA, 1);
    lA += __shfl_xor_sync(0xffffffffu, lA, 2);
    lB += __shfl_xor_sync(0xffffffffu, lB, 1);
    lB += __shfl_xor_sync(0xffffffffu, lB, 2);

    const size_t slot = ((size_t)spl * NB + b) * NQT + qt;
    float* op = g_Op + slot * 64 * 64;
#pragma unroll
    for (int nt = 0; nt < 8; ++nt) {
        *reinterpret_cast<float2*>(op + (w16 + g) * 64 + nt * 8 + 2 * t) =
            make_float2(o[nt][0], o[nt][1]);
        *reinterpret_cast<float2*>(op + (w16 + g + 8) * 64 + nt * 8 + 2 * t) =
            make_float2(o[nt][2], o[nt][3]);
    }
    if (t == 0) {
        g_M[slot * 64 + w16 + g]     = mA;
        g_M[slot * 64 + w16 + g + 8] = mB;
        g_L[slot * 64 + w16 + g]     = lA;
        g_L[slot * 64 + w16 + g + 8] = lB;
    }
}

// ---------------------------------------------------------------------------
// Kernel 3: merge NSPL split-K partials. grid (32, NB), 256 threads.
// ---------------------------------------------------------------------------
__global__ __launch_bounds__(256) void merge_kernel(float* __restrict__ out)
{
    const int qt  = blockIdx.x;
    const int b   = blockIdx.y;
    const int tid = threadIdx.x;
    const int r   = tid >> 2;
    const int cs  = (tid & 3) * 16;

    size_t slot[NSPL];
    float  m[NSPL], l[NSPL];
    float  M = -1e30f;
#pragma unroll
    for (int s = 0; s < NSPL; ++s) {
        slot[s] = ((size_t)s * NB + b) * NQT + qt;
        m[s] = g_M[slot[s] * 64 + r];
        l[s] = g_L[slot[s] * 64 + r];
        M = fmaxf(M, m[s]);
    }
    float f[NSPL], den = 0.0f;
#pragma unroll
    for (int s = 0; s < NSPL; ++s) {
        f[s] = __expf(m[s] - M);     // empty split: exp(-1e30 - M) = 0
        den += l[s] * f[s];
    }
    const float inv = 1.0f / den;
#pragma unroll
    for (int s = 0; s < NSPL; ++s) f[s] *= inv;

    float4* po = reinterpret_cast<float4*>(
        out + ((size_t)b * NS + qt * 64 + r) * NH + cs);

#pragma unroll
    for (int u = 0; u < 4; ++u) {
        float4 acc = make_float4(0.f, 0.f, 0.f, 0.f);
#pragma unroll
        for (int s = 0; s < NSPL; ++s) {
            float4 v = *reinterpret_cast<const float4*>(
                g_Op + slot[s] * 4096 + r * 64 + cs + u * 4);
            acc.x += v.x * f[s]; acc.y += v.y * f[s];
            acc.z += v.z * f[s]; acc.w += v.w * f[s];
        }
        po[u] = acc;
    }
}

// ---------------------------------------------------------------------------
extern "C" void kernel_launch(void* const* d_in, const int* in_sizes, int n_in,
                              void* d_out, int out_size)
{
    const float* X  = (const float*)d_in[0];
    const float* Wq = (const float*)d_in[1];
    const float* Wk = (const float*)d_in[2];
    const float* Wv = (const float*)d_in[3];
    float* out = (float*)d_out;

    const int attn_smem = 3 * 64 * SKA * (int)sizeof(float);   // 52224 B
    cudaFuncSetAttribute(attn_kernel,
                         cudaFuncAttributeMaxDynamicSharedMemorySize, attn_smem);

    proj_kernel<<<dim3((NB * NS) / 128, 1, 3), 128>>>(X, Wq, Wk, Wv);
    attn_kernel<<<dim3(NQT, NB, NSPL), 128, attn_smem>>>();
    merge_kernel<<<dim3(NQT, NB), 256>>>(out);
}

// round 13
// speedup vs baseline: 1.3176x; 1.1322x over previous
#include <cuda_runtime.h>

#define NB 8
#define NS 2048
#define ND 768
#define NH 64
#define NQT 32            // q-tiles of 64
#define NSPL 4            // split-K factor
#define SKA 68            // attn smem stride (floats), 68 % 32 == 4 -> conflict-free LDSM
#define STG (64 * SKA)    // floats per K/V buffer

// g_Q, g_K: [b][n][h] tf32 bits.  g_V: [b][h][n] tf32 bits (pre-transposed).
__device__ float g_Q[NB * NS * NH];
__device__ float g_K[NB * NS * NH];
__device__ float g_V[NB * NH * NS];

// split-K partials: [split][b][qt] -> 64x64 unnormalized O, plus per-row m,l
__device__ float g_Op[NSPL * NB * NQT * 64 * 64];
__device__ float g_M[NSPL * NB * NQT * 64];
__device__ float g_L[NSPL * NB * NQT * 64];

// ---------------------------------------------------------------------------
// helpers
// ---------------------------------------------------------------------------
__device__ __forceinline__ unsigned f2tf(float f) {
    unsigned u;
    asm("cvt.rna.tf32.f32 %0, %1;" : "=r"(u) : "f"(f));
    return u;
}
__device__ __forceinline__ uint4 f4tf(float4 v) {
    uint4 r;
    r.x = f2tf(v.x); r.y = f2tf(v.y); r.z = f2tf(v.z); r.w = f2tf(v.w);
    return r;
}
__device__ __forceinline__ void mma8(float c[4],
                                     unsigned a0, unsigned a1, unsigned a2, unsigned a3,
                                     unsigned b0, unsigned b1) {
    asm("mma.sync.aligned.m16n8k8.row.col.f32.tf32.tf32.f32 "
        "{%0,%1,%2,%3}, {%4,%5,%6,%7}, {%8,%9}, {%0,%1,%2,%3};"
        : "+f"(c[0]), "+f"(c[1]), "+f"(c[2]), "+f"(c[3])
        : "r"(a0), "r"(a1), "r"(a2), "r"(a3), "r"(b0), "r"(b1));
}
__device__ __forceinline__ void ldsm4(unsigned &r0, unsigned &r1,
                                      unsigned &r2, unsigned &r3, unsigned addr) {
    asm volatile("ldmatrix.sync.aligned.m8n8.x4.shared.b16 {%0,%1,%2,%3}, [%4];"
                 : "=r"(r0), "=r"(r1), "=r"(r2), "=r"(r3) : "r"(addr));
}
__device__ __forceinline__ void cpa16(unsigned dst, const void* src) {
    asm volatile("cp.async.cg.shared.global [%0], [%1], 16;"
                 :: "r"(dst), "l"(src));
}
#define CP_COMMIT() asm volatile("cp.async.commit_group;" ::: "memory")
#define CP_WAIT0()  asm volatile("cp.async.wait_group 0;" ::: "memory")

// ---------------------------------------------------------------------------
// Kernel 1: QKV projection via tf32 mma (proven R12 version).
// Epilogue stores tf32-rounded bits; V stored transposed g_V[b][h][n].
// ---------------------------------------------------------------------------
#define XS_S 36
#define WS_S 72

__global__ __launch_bounds__(128, 3) void proj_kernel(
    const float* __restrict__ X,
    const float* __restrict__ Wq,
    const float* __restrict__ Wk,
    const float* __restrict__ Wv)
{
    const int z = blockIdx.z;
    const float* __restrict__ W = (z == 0) ? Wq : (z == 1) ? Wk : Wv;

    __shared__ float Xs[128 * XS_S];
    __shared__ float Ws[32 * WS_S];

    const int row0 = blockIdx.x * 128;
    const int tid  = threadIdx.x;
    const int wrp  = tid >> 5;
    const int lane = tid & 31;
    const int g    = lane >> 2;
    const int t    = lane & 3;
    const int mrow = wrp * 32;

    float acc[2][8][4];
#pragma unroll
    for (int mt = 0; mt < 2; ++mt)
#pragma unroll
        for (int nt = 0; nt < 8; ++nt)
#pragma unroll
            for (int r = 0; r < 4; ++r) acc[mt][nt][r] = 0.0f;

    const int xr = tid >> 3;
    const int xc = (tid & 7) * 4;
    const int wr = tid >> 4;
    const int wc = (tid & 15) * 4;

    for (int kk = 0; kk < ND; kk += 32) {
#pragma unroll
        for (int it = 0; it < 8; ++it) {
            const int r = xr + it * 16;
            float4 v = *reinterpret_cast<const float4*>(
                X + (size_t)(row0 + r) * ND + kk + xc);
            *reinterpret_cast<uint4*>(&Xs[r * XS_S + xc]) = f4tf(v);
        }
#pragma unroll
        for (int it = 0; it < 4; ++it) {
            const int r = wr + it * 8;
            float4 v = *reinterpret_cast<const float4*>(
                W + (size_t)(kk + r) * NH + wc);
            *reinterpret_cast<uint4*>(&Ws[r * WS_S + wc]) = f4tf(v);
        }
        __syncthreads();

#pragma unroll
        for (int dc = 0; dc < 4; ++dc) {
            unsigned a[2][4];
#pragma unroll
            for (int mt = 0; mt < 2; ++mt) {
                const int rb = mrow + mt * 16;
                a[mt][0] = __float_as_uint(Xs[(rb + g)     * XS_S + dc * 8 + t]);
                a[mt][1] = __float_as_uint(Xs[(rb + g + 8) * XS_S + dc * 8 + t]);
                a[mt][2] = __float_as_uint(Xs[(rb + g)     * XS_S + dc * 8 + t + 4]);
                a[mt][3] = __float_as_uint(Xs[(rb + g + 8) * XS_S + dc * 8 + t + 4]);
            }
#pragma unroll
            for (int nt = 0; nt < 8; ++nt) {
                unsigned b0 = __float_as_uint(Ws[(dc * 8 + t)     * WS_S + nt * 8 + g]);
                unsigned b1 = __float_as_uint(Ws[(dc * 8 + t + 4) * WS_S + nt * 8 + g]);
                mma8(acc[0][nt], a[0][0], a[0][1], a[0][2], a[0][3], b0, b1);
                mma8(acc[1][nt], a[1][0], a[1][1], a[1][2], a[1][3], b0, b1);
            }
        }
        __syncthreads();
    }

#pragma unroll
    for (int mt = 0; mt < 2; ++mt) {
        const int rb = row0 + mrow + mt * 16;
#pragma unroll
        for (int nt = 0; nt < 8; ++nt) {
            const int col = nt * 8 + 2 * t;
            const int rA = rb + g, rB = rb + g + 8;
            const unsigned v0 = f2tf(acc[mt][nt][0]);
            const unsigned v1 = f2tf(acc[mt][nt][1]);
            const unsigned v2 = f2tf(acc[mt][nt][2]);
            const unsigned v3 = f2tf(acc[mt][nt][3]);
            if (z == 2) {
                const int bA = rA >> 11, nA = rA & 2047;
                const int bB = rB >> 11, nB = rB & 2047;
                g_V[((size_t)bA * NH + col)     * NS + nA] = __uint_as_float(v0);
                g_V[((size_t)bA * NH + col + 1) * NS + nA] = __uint_as_float(v1);
                g_V[((size_t)bB * NH + col)     * NS + nB] = __uint_as_float(v2);
                g_V[((size_t)bB * NH + col + 1) * NS + nB] = __uint_as_float(v3);
            } else {
                float* __restrict__ Out = (z == 0) ? g_Q : g_K;
                *reinterpret_cast<uint2*>(Out + (size_t)rA * NH + col) =
                    make_uint2(v0, v1);
                *reinterpret_cast<uint2*>(Out + (size_t)rB * NH + col) =
                    make_uint2(v2, v3);
            }
        }
    }
}

// ---------------------------------------------------------------------------
// Kernel 2: causal flash attention, tf32 mma + ldmatrix + split-K x4 +
// cp.async double-buffered K/V pipeline.
// smem: K0 | V0 | K1 | V1 (each 64x68). P reuses the CURRENT K buffer
// (syncthreads after S makes that safe). Next tile's K/V prefetched via
// cp.async during current tile's compute.
// ---------------------------------------------------------------------------
__global__ __launch_bounds__(128, 3) void attn_kernel()
{
    extern __shared__ float sm[];

    const int b    = blockIdx.y;
    const int qt   = (NQT - 1) - blockIdx.x;
    const int spl  = blockIdx.z;
    const int q0   = qt * 64;
    const int tid  = threadIdx.x;
    const int wrp  = tid >> 5;
    const int lane = tid & 31;
    const int g    = lane >> 2;
    const int t    = lane & 3;
    const int w16  = wrp * 16;

    const int T  = qt + 1;
    const int tb = (T * spl) >> 2;
    const int te = (T * (spl + 1)) >> 2;

    const float* __restrict__ Qb = g_Q + (size_t)b * NS * NH;
    const float* __restrict__ Kb = g_K + (size_t)b * NS * NH;
    const float* __restrict__ Vb = g_V + (size_t)b * NH * NS;

    const unsigned smb = (unsigned)__cvta_generic_to_shared(sm);
    // fragment lane offsets (byte) within a buffer
    const int rowA = w16 + (lane & 15);
    const int colA = (lane >> 4) * 4;
    const unsigned fragA = (unsigned)((rowA * SKA + colA) * 4);
    const int rowB = (lane & 7) | ((lane >> 1) & 8);
    const int colB = ((lane >> 3) & 1) * 4;
    const unsigned fragB = (unsigned)((rowB * SKA + colB) * 4);
    // buffer byte offsets: K0=0, V0=1, K1=2, V1=3
    const unsigned bufK[2] = { 0u, 2u * STG * 4 };
    const unsigned bufV[2] = { 1u * STG * 4, 3u * STG * 4 };

    // per-thread load coordinates (one row, half a row of float4s)
    const int lr  = tid >> 1;
    const int lc  = (tid & 1) * 32;
    const unsigned kdst0 = (unsigned)((lr * SKA + lc) * 4);
    const float* ksrc_base = Kb + (size_t)lr * NH + lc;   // + k0*NH
    const float* vsrc_base = Vb + (size_t)lr * NS + lc;   // + k0

    // ---- stage Q through K0, hoist A-fragments into registers ----
    unsigned qf[8][4];
    if (tb < te) {
        const float4* qp = reinterpret_cast<const float4*>(
            Qb + (size_t)(q0 + lr) * NH + lc);
#pragma unroll
        for (int u = 0; u < 8; ++u)
            *reinterpret_cast<float4*>(&sm[lr * SKA + lc + u * 4]) = qp[u];
        __syncthreads();
#pragma unroll
        for (int dc = 0; dc < 8; ++dc)
            ldsm4(qf[dc][0], qf[dc][1], qf[dc][2], qf[dc][3],
                  smb + fragA + dc * 32);
        __syncthreads();   // Q reads done before prefetch overwrites K0

        // ---- prologue: prefetch first tile into buffer 0 ----
        {
            const int k0 = tb * 64;
            const float* ks = ksrc_base + (size_t)k0 * NH;
            const float* vs = vsrc_base + k0;
#pragma unroll
            for (int u = 0; u < 8; ++u) {
                cpa16(smb + bufK[0] + kdst0 + u * 16, ks + u * 4);
                cpa16(smb + bufV[0] + kdst0 + u * 16, vs + u * 4);
            }
            CP_COMMIT();
        }
    }

    float o[8][4];
#pragma unroll
    for (int nt = 0; nt < 8; ++nt)
#pragma unroll
        for (int r = 0; r < 4; ++r) o[nt][r] = 0.0f;
    float mA = -1e30f, mB = -1e30f;
    float lA = 0.0f,   lB = 0.0f;

    int cur = 0;
    for (int kt = tb; kt < te; ++kt) {
        CP_WAIT0();
        __syncthreads();   // buf[cur] ready; all warps done with buf[cur^1]

        // prefetch next tile into the other buffer (overlaps this tile's math)
        if (kt + 1 < te) {
            const int k0n = (kt + 1) * 64;
            const float* ks = ksrc_base + (size_t)k0n * NH;
            const float* vs = vsrc_base + k0n;
#pragma unroll
            for (int u = 0; u < 8; ++u) {
                cpa16(smb + bufK[cur ^ 1] + kdst0 + u * 16, ks + u * 4);
                cpa16(smb + bufV[cur ^ 1] + kdst0 + u * 16, vs + u * 4);
            }
            CP_COMMIT();
        }

        // ---- S = Q K^T from K[cur] ----
        float s[8][4];
#pragma unroll
        for (int nt = 0; nt < 8; ++nt)
#pragma unroll
            for (int r = 0; r < 4; ++r) s[nt][r] = 0.0f;

        const unsigned bKc = smb + bufK[cur] + fragB;
#pragma unroll
        for (int dc = 0; dc < 8; ++dc) {
#pragma unroll
            for (int p = 0; p < 4; ++p) {
                unsigned b0, b1, b2, b3;
                ldsm4(b0, b1, b2, b3, bKc + p * (16 * SKA * 4) + dc * 32);
                mma8(s[2 * p],     qf[dc][0], qf[dc][1], qf[dc][2], qf[dc][3], b0, b1);
                mma8(s[2 * p + 1], qf[dc][0], qf[dc][1], qf[dc][2], qf[dc][3], b2, b3);
            }
        }

        if (kt == qt) {
            const int rA = w16 + g, rB = w16 + g + 8;
#pragma unroll
            for (int nt = 0; nt < 8; ++nt) {
                const int c0 = nt * 8 + 2 * t, c1 = c0 + 1;
                s[nt][0] = (c0 <= rA) ? s[nt][0] * 0.125f : -1e30f;
                s[nt][1] = (c1 <= rA) ? s[nt][1] * 0.125f : -1e30f;
                s[nt][2] = (c0 <= rB) ? s[nt][2] * 0.125f : -1e30f;
                s[nt][3] = (c1 <= rB) ? s[nt][3] * 0.125f : -1e30f;
            }
        } else {
#pragma unroll
            for (int nt = 0; nt < 8; ++nt)
#pragma unroll
                for (int r = 0; r < 4; ++r) s[nt][r] *= 0.125f;
        }

        // ---- online softmax ----
        float cmA = -1e30f, cmB = -1e30f;
#pragma unroll
        for (int nt = 0; nt < 8; ++nt) {
            cmA = fmaxf(cmA, fmaxf(s[nt][0], s[nt][1]));
            cmB = fmaxf(cmB, fmaxf(s[nt][2], s[nt][3]));
        }
        cmA = fmaxf(cmA, __shfl_xor_sync(0xffffffffu, cmA, 1));
        cmA = fmaxf(cmA, __shfl_xor_sync(0xffffffffu, cmA, 2));
        cmB = fmaxf(cmB, __shfl_xor_sync(0xffffffffu, cmB, 1));
        cmB = fmaxf(cmB, __shfl_xor_sync(0xffffffffu, cmB, 2));

        const float mnA = fmaxf(mA, cmA);
        const float mnB = fmaxf(mB, cmB);
        const float cA  = __expf(mA - mnA);
        const float cB  = __expf(mB - mnB);
        mA = mnA; mB = mnB;
        lA *= cA; lB *= cB;
#pragma unroll
        for (int nt = 0; nt < 8; ++nt) {
            o[nt][0] *= cA; o[nt][1] *= cA;
            o[nt][2] *= cB; o[nt][3] *= cB;
        }
#pragma unroll
        for (int nt = 0; nt < 8; ++nt) {
            s[nt][0] = __expf(s[nt][0] - mnA);
            s[nt][1] = __expf(s[nt][1] - mnA);
            s[nt][2] = __expf(s[nt][2] - mnB);
            s[nt][3] = __expf(s[nt][3] - mnB);
            lA += s[nt][0] + s[nt][1];
            lB += s[nt][2] + s[nt][3];
        }

        __syncthreads();   // all S reads of K[cur] done -> safe to overwrite with P

        // ---- P -> K[cur] rows (tf32 bits) ----
        float* Kcur = sm + (cur ? 2 * STG : 0);
#pragma unroll
        for (int nt = 0; nt < 8; ++nt) {
            *reinterpret_cast<uint2*>(&Kcur[(w16 + g) * SKA + nt * 8 + 2 * t]) =
                make_uint2(f2tf(s[nt][0]), f2tf(s[nt][1]));
            *reinterpret_cast<uint2*>(&Kcur[(w16 + g + 8) * SKA + nt * 8 + 2 * t]) =
                make_uint2(f2tf(s[nt][2]), f2tf(s[nt][3]));
        }
        __syncwarp();

        // ---- O += P V from V[cur] ----
        const unsigned aPc = smb + bufK[cur] + fragA;
        const unsigned bVc = smb + bufV[cur] + fragB;
#pragma unroll
        for (int kc = 0; kc < 8; ++kc) {
            unsigned a0, a1, a2, a3;
            ldsm4(a0, a1, a2, a3, aPc + kc * 32);
#pragma unroll
            for (int p = 0; p < 4; ++p) {
                unsigned b0, b1, b2, b3;
                ldsm4(b0, b1, b2, b3, bVc + p * (16 * SKA * 4) + kc * 32);
                mma8(o[2 * p],     a0, a1, a2, a3, b0, b1);
                mma8(o[2 * p + 1], a0, a1, a2, a3, b2, b3);
            }
        }

        cur ^= 1;
    }

    lA += __shfl_xor_sync(0xffffffffu, lA, 1);
    lA += __shfl_xor_sync(0xffffffffu, lA, 2);
    lB += __shfl_xor_sync(0xffffffffu, lB, 1);
    lB += __shfl_xor_sync(0xffffffffu, lB, 2);

    const size_t slot = ((size_t)spl * NB + b) * NQT + qt;
    float* op = g_Op + slot * 64 * 64;
#pragma unroll
    for (int nt = 0; nt < 8; ++nt) {
        *reinterpret_cast<float2*>(op + (w16 + g) * 64 + nt * 8 + 2 * t) =
            make_float2(o[nt][0], o[nt][1]);
        *reinterpret_cast<float2*>(op + (w16 + g + 8) * 64 + nt * 8 + 2 * t) =
            make_float2(o[nt][2], o[nt][3]);
    }
    if (t == 0) {
        g_M[slot * 64 + w16 + g]     = mA;
        g_M[slot * 64 + w16 + g + 8] = mB;
        g_L[slot * 64 + w16 + g]     = lA;
        g_L[slot * 64 + w16 + g + 8] = lB;
    }
}

// ---------------------------------------------------------------------------
// Kernel 3: merge NSPL split-K partials. grid (32, NB), 256 threads.
// ---------------------------------------------------------------------------
__global__ __launch_bounds__(256) void merge_kernel(float* __restrict__ out)
{
    const int qt  = blockIdx.x;
    const int b   = blockIdx.y;
    const int tid = threadIdx.x;
    const int r   = tid >> 2;
    const int cs  = (tid & 3) * 16;

    size_t slot[NSPL];
    float  m[NSPL], l[NSPL];
    float  M = -1e30f;
#pragma unroll
    for (int s = 0; s < NSPL; ++s) {
        slot[s] = ((size_t)s * NB + b) * NQT + qt;
        m[s] = g_M[slot[s] * 64 + r];
        l[s] = g_L[slot[s] * 64 + r];
        M = fmaxf(M, m[s]);
    }
    float f[NSPL], den = 0.0f;
#pragma unroll
    for (int s = 0; s < NSPL; ++s) {
        f[s] = __expf(m[s] - M);     // empty split: exp(-1e30 - M) = 0
        den += l[s] * f[s];
    }
    const float inv = 1.0f / den;
#pragma unroll
    for (int s = 0; s < NSPL; ++s) f[s] *= inv;

    float4* po = reinterpret_cast<float4*>(
        out + ((size_t)b * NS + qt * 64 + r) * NH + cs);

#pragma unroll
    for (int u = 0; u < 4; ++u) {
        float4 acc = make_float4(0.f, 0.f, 0.f, 0.f);
#pragma unroll
        for (int s = 0; s < NSPL; ++s) {
            float4 v = *reinterpret_cast<const float4*>(
                g_Op + slot[s] * 4096 + r * 64 + cs + u * 4);
            acc.x += v.x * f[s]; acc.y += v.y * f[s];
            acc.z += v.z * f[s]; acc.w += v.w * f[s];
        }
        po[u] = acc;
    }
}

// ---------------------------------------------------------------------------
extern "C" void kernel_launch(void* const* d_in, const int* in_sizes, int n_in,
                              void* d_out, int out_size)
{
    const float* X  = (const float*)d_in[0];
    const float* Wq = (const float*)d_in[1];
    const float* Wk = (const float*)d_in[2];
    const float* Wv = (const float*)d_in[3];
    float* out = (float*)d_out;

    const int attn_smem = 4 * STG * (int)sizeof(float);   // 69632 B
    cudaFuncSetAttribute(attn_kernel,
                         cudaFuncAttributeMaxDynamicSharedMemorySize, attn_smem);

    proj_kernel<<<dim3((NB * NS) / 128, 1, 3), 128>>>(X, Wq, Wk, Wv);
    attn_kernel<<<dim3(NQT, NB, NSPL), 128, attn_smem>>>();
    merge_kernel<<<dim3(NQT, NB), 256>>>(out);
}